// round 5
// baseline (speedup 1.0000x reference)
#include <cuda_runtime.h>
#include <cuda_bf16.h>
#include <cstdint>

// ============================================================================
// Head_13: fused causal single-head attention. B=1024 T=128 C=384 HS=64 fp32.
// mma.sync m16n8k16 bf16 (baseline PTX, works on plain sm_103 target) with
// hi/lo split emulation (3 MMAs per product => ~fp32 accuracy).
// One CTA per batch element, 256 threads (8 warps, 4x2 grid).
// ============================================================================

#define T_DIM 128
#define H_DIM 64

// row strides (bytes) — padded, conflict-free for ldmatrix (16B * row % 128B distinct)
#define XSTR 144   // 64 bf16 + 16B pad
#define WSTR 144
#define QSTR 144
#define VSTR 272   // 128 bf16 + 16B pad
#define PSTR 272
#define SSTRW 129  // floats per S row (129 % 32 == 1 -> conflict-free)

// ---- smem offsets ----
// Region A (phase 1 X/W; later S fp32)
#define XH_OFF 0
#define XL_OFF 18432
#define WH_OFF 36864
#define WL_OFF 64512
#define S_OFF  0                 // 128*129*4 = 66048 <= 92160
// Region B (Q/K hi/lo; later P hi/lo)
#define QH_OFF 92160
#define QL_OFF 110592
#define KH_OFF 129024
#define KL_OFF 147456
#define PH_OFF 92160             // 128*272 = 34816
#define PL_OFF 126976
// Region C (V^T hi/lo)
#define VTH_OFF 165888           // 64*272 = 17408
#define VTL_OFF 183296
#define SMEM_TOTAL 200704

// Pre-split, padded weight images: 6 chunks x [192 rows x 144B]
__device__ __align__(16) unsigned char g_wh[6 * 27648];
__device__ __align__(16) unsigned char g_wl[6 * 27648];

// ---------------------------------------------------------------------------
__device__ __forceinline__ uint32_t smem_u32(const void* p) {
    uint32_t a;
    asm("{ .reg .u64 t; cvta.to.shared.u64 t, %1; cvt.u32.u64 %0, t; }"
        : "=r"(a) : "l"(p));
    return a;
}
// fp32 -> bf16 hi + bf16 lo (residual)
__device__ __forceinline__ void split2(float v, unsigned short& h, unsigned short& l) {
    __nv_bfloat16 hb = __float2bfloat16(v);
    float r = v - __bfloat162float(hb);
    __nv_bfloat16 lb = __float2bfloat16(r);
    h = __bfloat16_as_ushort(hb);
    l = __bfloat16_as_ushort(lb);
}
__device__ __forceinline__ uint32_t pack2(unsigned short a, unsigned short b) {
    return (uint32_t)a | ((uint32_t)b << 16);
}
__device__ __forceinline__ void ldmx4(uint32_t* r, uint32_t addr) {
    asm volatile("ldmatrix.sync.aligned.m8n8.x4.shared.b16 {%0,%1,%2,%3}, [%4];"
                 : "=r"(r[0]), "=r"(r[1]), "=r"(r[2]), "=r"(r[3]) : "r"(addr));
}
__device__ __forceinline__ void ldmx2(uint32_t* r, uint32_t addr) {
    asm volatile("ldmatrix.sync.aligned.m8n8.x2.shared.b16 {%0,%1}, [%2];"
                 : "=r"(r[0]), "=r"(r[1]) : "r"(addr));
}
__device__ __forceinline__ void mma16816(float* d, const uint32_t* a, const uint32_t* b) {
    asm volatile(
        "mma.sync.aligned.m16n8k16.row.col.f32.bf16.bf16.f32 "
        "{%0,%1,%2,%3}, {%4,%5,%6,%7}, {%8,%9}, {%0,%1,%2,%3};"
        : "+f"(d[0]), "+f"(d[1]), "+f"(d[2]), "+f"(d[3])
        : "r"(a[0]), "r"(a[1]), "r"(a[2]), "r"(a[3]), "r"(b[0]), "r"(b[1]));
}

// ---------------------------------------------------------------------------
// Prep: stacked transposed weights Wt[192][384] (rows 0-63 Wq^T, 64-127 Wk^T,
// 128-191 Wv^T), hi/lo split, padded chunk images in gmem scratch.
// ---------------------------------------------------------------------------
__global__ void prep_kernel(const float* __restrict__ Wq,
                            const float* __restrict__ Wk,
                            const float* __restrict__ Wv) {
    int idx = blockIdx.x * 256 + threadIdx.x;
    if (idx >= 192 * 384) return;
    int n = idx / 384, c = idx % 384;
    float w;
    if (n < 64)       w = Wq[c * 64 + n];
    else if (n < 128) w = Wk[c * 64 + (n - 64)];
    else              w = Wv[c * 64 + (n - 128)];
    unsigned short h, l;
    split2(w, h, l);
    int chunk = c >> 6, j = c & 63;
    uint32_t off = (uint32_t)chunk * 27648u + (uint32_t)n * WSTR + j * 2;
    *(unsigned short*)(g_wh + off) = h;
    *(unsigned short*)(g_wl + off) = l;
}

// ---------------------------------------------------------------------------
__global__ void __launch_bounds__(256, 1)
attn_kernel(const float* __restrict__ x, float* __restrict__ out) {
    extern __shared__ __align__(16) char sm[];
    const uint32_t smb = smem_u32(sm);
    const int tid  = threadIdx.x;
    const int lane = tid & 31;
    const int w    = tid >> 5;
    const int wm   = w >> 1;      // 0..3 : 32-row block
    const int wn   = w & 1;       // 0..1 : column half
    const int b    = blockIdx.x;

    // ================= phase 1: [Q|K|V] = x @ Wt^T ==================
    float acc[2][12][4];
#pragma unroll
    for (int i = 0; i < 2; i++)
#pragma unroll
        for (int j = 0; j < 12; j++)
#pragma unroll
            for (int k = 0; k < 4; k++) acc[i][j][k] = 0.f;

    const float* xb = x + (size_t)b * (T_DIM * 384);
    for (int chunk = 0; chunk < 6; chunk++) {
        if (chunk) __syncthreads();  // previous MMA reads done before refill
        // x chunk [128 x 64] fp32 -> hi/lo bf16
        const float4* xs = (const float4*)(xb + chunk * 64);
#pragma unroll
        for (int it = 0; it < 8; it++) {
            int i = tid + it * 256;
            int t = i >> 4, f4 = i & 15;
            float4 v = xs[t * 96 + f4];
            unsigned short h0, h1, h2, h3, l0, l1, l2, l3;
            split2(v.x, h0, l0); split2(v.y, h1, l1);
            split2(v.z, h2, l2); split2(v.w, h3, l3);
            uint32_t off = (uint32_t)t * XSTR + f4 * 8;
            *(uint2*)(sm + XH_OFF + off) = make_uint2(pack2(h0, h1), pack2(h2, h3));
            *(uint2*)(sm + XL_OFF + off) = make_uint2(pack2(l0, l1), pack2(l2, l3));
        }
        // W chunk: flat 16B copies of pre-split padded image
        const uint4* wsh = (const uint4*)(g_wh + chunk * 27648);
        const uint4* wsl = (const uint4*)(g_wl + chunk * 27648);
        uint4* wdh = (uint4*)(sm + WH_OFF);
        uint4* wdl = (uint4*)(sm + WL_OFF);
        for (int i = tid; i < 1728; i += 256) { wdh[i] = wsh[i]; wdl[i] = wsl[i]; }
        __syncthreads();

#pragma unroll
        for (int split = 0; split < 3; split++) {
            uint32_t xoff = (split == 2) ? XL_OFF : XH_OFF;
            uint32_t woff = (split == 1) ? WL_OFF : WH_OFF;
#pragma unroll
            for (int ks = 0; ks < 4; ks++) {
                uint32_t a[2][4];
#pragma unroll
                for (int mt = 0; mt < 2; mt++)
                    ldmx4(a[mt], smb + xoff + (wm * 32 + mt * 16 + (lane & 15)) * XSTR
                                 + ks * 32 + (lane >> 4) * 16);
#pragma unroll
                for (int nt = 0; nt < 12; nt++) {
                    uint32_t bb[2];
                    ldmx2(bb, smb + woff + (wn * 96 + nt * 8 + (lane & 7)) * WSTR
                              + ks * 32 + ((lane >> 3) & 1) * 16);
                    mma16816(acc[0][nt], a[0], bb);
                    mma16816(acc[1][nt], a[1], bb);
                }
            }
        }
    }
    __syncthreads();

    // write Q/K (K-major hi/lo) and V^T (hi/lo)
    const int rbase = wm * 32 + (lane >> 2);
#pragma unroll
    for (int mt = 0; mt < 2; mt++) {
        int r = rbase + mt * 16;
#pragma unroll
        for (int nt = 0; nt < 12; nt++) {
            int g = wn * 96 + nt * 8 + 2 * (lane & 3);
            unsigned short h0, l0, h1, l1, h2, l2, h3, l3;
            split2(acc[mt][nt][0], h0, l0); split2(acc[mt][nt][1], h1, l1);
            split2(acc[mt][nt][2], h2, l2); split2(acc[mt][nt][3], h3, l3);
            if (g < 128) {
                uint32_t bh = (g < 64) ? QH_OFF : KH_OFF;
                uint32_t bl = (g < 64) ? QL_OFF : KL_OFF;
                int gc = g & 63;
                *(uint32_t*)(sm + bh + (uint32_t)r * QSTR + gc * 2)       = pack2(h0, h1);
                *(uint32_t*)(sm + bl + (uint32_t)r * QSTR + gc * 2)       = pack2(l0, l1);
                *(uint32_t*)(sm + bh + (uint32_t)(r + 8) * QSTR + gc * 2) = pack2(h2, h3);
                *(uint32_t*)(sm + bl + (uint32_t)(r + 8) * QSTR + gc * 2) = pack2(l2, l3);
            } else {
                int hc = g - 128;  // V^T row
                *(unsigned short*)(sm + VTH_OFF + (uint32_t)hc * VSTR + r * 2)             = h0;
                *(unsigned short*)(sm + VTL_OFF + (uint32_t)hc * VSTR + r * 2)             = l0;
                *(unsigned short*)(sm + VTH_OFF + (uint32_t)(hc + 1) * VSTR + r * 2)       = h1;
                *(unsigned short*)(sm + VTL_OFF + (uint32_t)(hc + 1) * VSTR + r * 2)       = l1;
                *(unsigned short*)(sm + VTH_OFF + (uint32_t)hc * VSTR + (r + 8) * 2)       = h2;
                *(unsigned short*)(sm + VTL_OFF + (uint32_t)hc * VSTR + (r + 8) * 2)       = l2;
                *(unsigned short*)(sm + VTH_OFF + (uint32_t)(hc + 1) * VSTR + (r + 8) * 2) = h3;
                *(unsigned short*)(sm + VTL_OFF + (uint32_t)(hc + 1) * VSTR + (r + 8) * 2) = l3;
            }
        }
    }
    __syncthreads();

    // ================= S = Q K^T (causal tiles only) =================
    {
        float sacc[2][8][4];
#pragma unroll
        for (int i = 0; i < 2; i++)
#pragma unroll
            for (int j = 0; j < 8; j++)
#pragma unroll
                for (int k = 0; k < 4; k++) sacc[i][j][k] = 0.f;

#pragma unroll
        for (int split = 0; split < 3; split++) {
            uint32_t qoff = (split == 2) ? QL_OFF : QH_OFF;
            uint32_t koff = (split == 1) ? KL_OFF : KH_OFF;
#pragma unroll
            for (int ks = 0; ks < 4; ks++) {
                uint32_t a[2][4];
#pragma unroll
                for (int mt = 0; mt < 2; mt++)
                    ldmx4(a[mt], smb + qoff + (wm * 32 + mt * 16 + (lane & 15)) * QSTR
                                 + ks * 32 + (lane >> 4) * 16);
#pragma unroll
                for (int nt = 0; nt < 8; nt++) {
                    int ncol = wn * 64 + nt * 8;
                    if (ncol <= wm * 32 + 31) {
                        uint32_t bb[2];
                        ldmx2(bb, smb + koff + (ncol + (lane & 7)) * QSTR
                                  + ks * 32 + ((lane >> 3) & 1) * 16);
                        if (ncol <= wm * 32 + 15) mma16816(sacc[0][nt], a[0], bb);
                        mma16816(sacc[1][nt], a[1], bb);
                    }
                }
            }
        }
        // S fp32 -> smem (stride 129 floats, conflict-free)
        float* sbuf = (float*)(sm + S_OFF);
#pragma unroll
        for (int mt = 0; mt < 2; mt++) {
            int r = rbase + mt * 16;
#pragma unroll
            for (int nt = 0; nt < 8; nt++) {
                int c = wn * 64 + nt * 8 + 2 * (lane & 3);
                sbuf[r * SSTRW + c]           = sacc[mt][nt][0];
                sbuf[r * SSTRW + c + 1]       = sacc[mt][nt][1];
                sbuf[(r + 8) * SSTRW + c]     = sacc[mt][nt][2];
                sbuf[(r + 8) * SSTRW + c + 1] = sacc[mt][nt][3];
            }
        }
    }
    __syncthreads();

    // ================= causal softmax (one row per thread) =================
    if (tid < T_DIM) {
        const int row = tid;
        const float* sr = (const float*)(sm + S_OFF) + row * SSTRW;
        float m = sr[0];
        for (int j = 1; j <= row; j++) m = fmaxf(m, sr[j]);
        float sum = 0.f;
        for (int j = 0; j <= row; j++) sum += __expf((sr[j] - m) * 0.125f);
        float inv = 1.f / sum;
        for (int j = 0; j < T_DIM; j += 2) {
            float e0 = (j     <= row) ? __expf((sr[j] - m) * 0.125f) * inv : 0.f;
            float e1 = (j + 1 <= row) ? __expf((sr[j + 1] - m) * 0.125f) * inv : 0.f;
            unsigned short h0, l0, h1, l1;
            split2(e0, h0, l0); split2(e1, h1, l1);
            uint32_t off = (uint32_t)row * PSTR + j * 2;
            *(uint32_t*)(sm + PH_OFF + off) = pack2(h0, h1);
            *(uint32_t*)(sm + PL_OFF + off) = pack2(l0, l1);
        }
    }
    __syncthreads();

    // ================= O = P V^T (skip all-zero k-tiles) =================
    {
        float oacc[2][4][4];
#pragma unroll
        for (int i = 0; i < 2; i++)
#pragma unroll
            for (int j = 0; j < 4; j++)
#pragma unroll
                for (int k = 0; k < 4; k++) oacc[i][j][k] = 0.f;

#pragma unroll
        for (int split = 0; split < 3; split++) {
            uint32_t aoff = (split == 2) ? PL_OFF : PH_OFF;
            uint32_t boff = (split == 1) ? VTL_OFF : VTH_OFF;
#pragma unroll
            for (int ks = 0; ks < 8; ks++) {
                if (ks * 16 <= wm * 32 + 31) {
                    uint32_t a[2][4];
#pragma unroll
                    for (int mt = 0; mt < 2; mt++)
                        ldmx4(a[mt], smb + aoff + (wm * 32 + mt * 16 + (lane & 15)) * PSTR
                                     + ks * 32 + (lane >> 4) * 16);
#pragma unroll
                    for (int nt = 0; nt < 4; nt++) {
                        uint32_t bb[2];
                        ldmx2(bb, smb + boff + (wn * 32 + nt * 8 + (lane & 7)) * VSTR
                                  + ks * 32 + ((lane >> 3) & 1) * 16);
                        if (ks * 16 <= wm * 32 + 15) mma16816(oacc[0][nt], a[0], bb);
                        mma16816(oacc[1][nt], a[1], bb);
                    }
                }
            }
        }
        // epilogue: fragments -> gmem
#pragma unroll
        for (int mt = 0; mt < 2; mt++) {
            int r = rbase + mt * 16;
#pragma unroll
            for (int nt = 0; nt < 4; nt++) {
                int c = wn * 32 + nt * 8 + 2 * (lane & 3);
                size_t o = ((size_t)b * T_DIM + r) * H_DIM + c;
                *(float2*)(out + o)             = make_float2(oacc[mt][nt][0], oacc[mt][nt][1]);
                *(float2*)(out + o + 8 * H_DIM) = make_float2(oacc[mt][nt][2], oacc[mt][nt][3]);
            }
        }
    }
}

// ---------------------------------------------------------------------------
extern "C" void kernel_launch(void* const* d_in, const int* in_sizes, int n_in,
                              void* d_out, int out_size) {
    const float* x  = (const float*)d_in[0];
    const float* Wq = (const float*)d_in[1];
    const float* Wk = (const float*)d_in[2];
    const float* Wv = (const float*)d_in[3];
    float* out = (float*)d_out;

    cudaFuncSetAttribute(attn_kernel,
                         cudaFuncAttributeMaxDynamicSharedMemorySize, SMEM_TOTAL);

    prep_kernel<<<(192 * 384 + 255) / 256, 256>>>(Wq, Wk, Wv);
    attn_kernel<<<1024, 256, SMEM_TOTAL>>>(x, out);
}